// round 17
// baseline (speedup 1.0000x reference)
#include <cuda_runtime.h>
#include <cuda_fp16.h>
#include <cstdint>
#include <cstddef>

#define BATCH 2
#define CC 128
#define HW 4096
#define HEADS 4
// 32^-0.5 * log2(e): softmax in base-2
#define SCALE2 0.25500526764086436f

// ---------------- scratch ----------------
__device__ __align__(16) __half g_qh[BATCH * CC * HW];
__device__ __align__(16) __half g_kh[BATCH * CC * HW];
__device__ __align__(16) __half g_vh[BATCH * CC * HW];
__device__ __align__(16) __half g_gdh[BATCH * HW * CC];   // guided, pixel-major
// folded conv2 ⊗ {Wk,Wv} weights (fp16, row stride 296) + folded biases
__device__ __align__(16) __half g_wk2[CC * 296];
__device__ __align__(16) __half g_wv2[CC * 296];
__device__ float g_bk2[CC];
__device__ float g_bv2[CC];

// ---------------- helpers ----------------
__device__ __forceinline__ uint32_t smem_u32(const void* p) {
    uint32_t a;
    asm("{ .reg .u64 t; cvta.to.shared.u64 t, %1; cvt.u32.u64 %0, t; }" : "=r"(a) : "l"(p));
    return a;
}
__device__ __forceinline__ float ex2f(float x) {
    float r; asm("ex2.approx.f32 %0, %1;" : "=f"(r) : "f"(x)); return r;
}
__device__ __forceinline__ uint32_t cvt_f16x2(float hi, float lo) {
    uint32_t r; asm("cvt.rn.f16x2.f32 %0, %1, %2;" : "=r"(r) : "f"(hi), "f"(lo)); return r;
}
__device__ __forceinline__ uint32_t ex2_h2(uint32_t a) {
    uint32_t r; asm("ex2.approx.f16x2 %0, %1;" : "=r"(r) : "r"(a)); return r;
}
__device__ __forceinline__ void ldsm4(uint32_t* r, uint32_t addr) {
    asm volatile("ldmatrix.sync.aligned.m8n8.x4.shared.b16 {%0,%1,%2,%3}, [%4];"
        : "=r"(r[0]), "=r"(r[1]), "=r"(r[2]), "=r"(r[3]) : "r"(addr));
}
__device__ __forceinline__ void ldsm4t(uint32_t* r, uint32_t addr) {
    asm volatile("ldmatrix.sync.aligned.m8n8.x4.trans.shared.b16 {%0,%1,%2,%3}, [%4];"
        : "=r"(r[0]), "=r"(r[1]), "=r"(r[2]), "=r"(r[3]) : "r"(addr));
}
__device__ __forceinline__ void mma16816(float* c, const uint32_t* a, const uint32_t* b) {
    asm volatile("mma.sync.aligned.m16n8k16.row.col.f32.f16.f16.f32 "
        "{%0,%1,%2,%3}, {%4,%5,%6,%7}, {%8,%9}, {%0,%1,%2,%3};"
        : "+f"(c[0]), "+f"(c[1]), "+f"(c[2]), "+f"(c[3])
        : "r"(a[0]), "r"(a[1]), "r"(a[2]), "r"(a[3]), "r"(b[0]), "r"(b[1]));
}
__device__ __forceinline__ void cp16(uint32_t saddr, const void* g) {
    asm volatile("cp.async.cg.shared.global [%0], [%1], 16;" :: "r"(saddr), "l"(g));
}
#define CP_COMMIT() asm volatile("cp.async.commit_group;" ::: "memory")
#define CP_WAIT1()  asm volatile("cp.async.wait_group 1;" ::: "memory")
#define CP_WAIT2()  asm volatile("cp.async.wait_group 2;" ::: "memory")

// ================================================================
// precompute: WkW2[co][k] = sum_co2 Wk[co][co2]*Wm2[co2][k] (fp16),
// folded biases. grid (288, 2), 128 threads.
// ================================================================
__global__ void precompute_w(const float* __restrict__ Wk, const float* __restrict__ bk,
                             const float* __restrict__ Wv, const float* __restrict__ bv,
                             const float* __restrict__ Wm2, const float* __restrict__ bm2) {
    int k = blockIdx.x;
    int mat = blockIdx.y;
    int co = threadIdx.x;
    const float* Wsel = mat ? Wv : Wk;
    float acc = 0.0f;
#pragma unroll 4
    for (int c2 = 0; c2 < CC; c2++)
        acc += Wsel[co * CC + c2] * Wm2[c2 * 288 + k];
    (mat ? g_wv2 : g_wk2)[co * 296 + k] = __float2half(acc);
    if (k == 0) {
        float bb = mat ? bv[co] : bk[co];
        for (int c2 = 0; c2 < CC; c2++)
            bb += Wsel[co * CC + c2] * bm2[c2];
        (mat ? g_bv2 : g_bk2)[co] = bb;
    }
}

// ================================================================
// fused QKV: grid (64 rows, BATCH, 2).
// z=0: seg -> conv1(relu) -> fp16 im2col B[64 px][296 k288] -> two
//      K=288 HMMA GEMMs with folded weights -> K, V fp16.
// z=1: Q 1x1 conv (K=128) pre-scaled -> Q fp16.
// smem: B [0, 37888), W [37888, 113664); sseg overlaps W start.
// ================================================================
#define B_OFF 0
#define W_OFF 37888
#define QKV_SMEM 113664

__global__ __launch_bounds__(256) void qkv_fused(
    const float* __restrict__ sr, const float* __restrict__ seg,
    const float* __restrict__ Wm1, const float* __restrict__ bm1,
    const float* __restrict__ Wq, const float* __restrict__ bq) {
    extern __shared__ __align__(16) char dsm[];
    const int tid = threadIdx.x;
    const int lane = tid & 31;
    const int w = tid >> 5;
    const int y = blockIdx.x, b = blockIdx.y;
    const bool isQ = (blockIdx.z == 1);
    const uint32_t sb = smem_u32(dsm);
    const int brow = (lane & 7) + ((lane & 16) >> 1);
    const int bcol8 = (lane & 8) ? 8 : 0;
    __half* hB = (__half*)(dsm + B_OFF);
    __half* hW = (__half*)(dsm + W_OFF);

    if (isQ) {
        // ---- stage Wq fp16 (row stride 296) + X tile from sr ----
#pragma unroll
        for (int i = 0; i < 16; i++) {
            int idx = i * 256 + tid;
            int co = idx >> 5, ci = (idx & 31) * 4;
            float4 v = *(const float4*)(Wq + co * CC + ci);
            __half* d = hW + co * 296 + ci;
            d[0] = __float2half(v.x); d[1] = __float2half(v.y);
            d[2] = __float2half(v.z); d[3] = __float2half(v.w);
        }
#pragma unroll
        for (int i = 0; i < 8; i++) {
            int idx = i * 256 + tid;
            int ci = idx >> 4, pxq = (idx & 15) * 4;
            float4 v = *(const float4*)(sr + ((size_t)b * CC + ci) * HW + y * 64 + pxq);
            hB[(pxq + 0) * 296 + ci] = __float2half(v.x);
            hB[(pxq + 1) * 296 + ci] = __float2half(v.y);
            hB[(pxq + 2) * 296 + ci] = __float2half(v.z);
            hB[(pxq + 3) * 296 + ci] = __float2half(v.w);
        }
        __syncthreads();

        float acc[2][4][4];
#pragma unroll
        for (int hf = 0; hf < 2; hf++)
#pragma unroll
            for (int nt = 0; nt < 4; nt++)
#pragma unroll
                for (int i = 0; i < 4; i++) acc[hf][nt][i] = 0.0f;
        const int arow = w * 16 + (lane & 15);
        const int acolb = (lane >> 4) * 8;
#pragma unroll
        for (int ks = 0; ks < 8; ks++) {
            uint32_t wa[4];
            ldsm4(wa, sb + W_OFF + (arow * 296 + ks * 16 + acolb) * 2);
#pragma unroll
            for (int hf = 0; hf < 2; hf++)
#pragma unroll
                for (int n0 = 0; n0 < 2; n0++) {
                    uint32_t bh[4];
                    ldsm4(bh, sb + B_OFF +
                          ((hf * 32 + n0 * 16 + brow) * 296 + ks * 16 + bcol8) * 2);
                    mma16816(acc[hf][n0 * 2], wa, bh);
                    mma16816(acc[hf][n0 * 2 + 1], wa, bh + 2);
                }
        }
        int coA = w * 16 + (lane >> 2);
        int coB = coA + 8;
        float bA = bq[coA], bB = bq[coB];
#pragma unroll
        for (int hf = 0; hf < 2; hf++) {
            size_t baseA = ((size_t)b * CC + coA) * HW + y * 64 + hf * 32;
            size_t baseB = ((size_t)b * CC + coB) * HW + y * 64 + hf * 32;
#pragma unroll
            for (int nt = 0; nt < 4; nt++) {
                int px = nt * 8 + 2 * (lane & 3);
                *(uint32_t*)(g_qh + baseA + px) =
                    cvt_f16x2((acc[hf][nt][1] + bA) * SCALE2,
                              (acc[hf][nt][0] + bA) * SCALE2);
                *(uint32_t*)(g_qh + baseB + px) =
                    cvt_f16x2((acc[hf][nt][3] + bB) * SCALE2,
                              (acc[hf][nt][2] + bB) * SCALE2);
            }
        }
        return;
    }

    // ================= z=0: mask conv1 -> im2col B, folded K/V GEMMs ========
    float* sseg = (float*)(dsm + W_OFF);   // dead once W staged
    const float* sgb = seg + (size_t)b * HW;
    for (int i = tid; i < 5 * 66; i += 256) {
        int r = i / 66, x = i % 66;
        int yy = y + r - 2, xx = x - 1;
        sseg[r * 66 + x] = (yy >= 0 && yy < 64 && xx >= 0 && xx < 64)
                           ? sgb[yy * 64 + xx] : 0.0f;
    }
    __syncthreads();
    // conv1 + relu; write fp16 value into <=3 im2col slots
    for (int i = tid; i < 32 * 3 * 66; i += 256) {
        int c = i / 198, rem = i % 198, r = rem / 66, x = rem % 66;
        int yy = y + r - 1, xx = x - 1;
        float v = 0.0f;
        if (yy >= 0 && yy < 64 && xx >= 0 && xx < 64) {
            float acc = bm1[c];
            const float* wp = Wm1 + c * 9;
#pragma unroll
            for (int dy = 0; dy < 3; dy++)
#pragma unroll
                for (int dx = 0; dx < 3; dx++)
                    acc += wp[dy * 3 + dx] * sseg[(r + dy) * 66 + x + dx - 1];
            v = fmaxf(acc, 0.0f);
        }
        __half hv = __float2half(v);
        int kb = c * 9 + r * 3;
#pragma unroll
        for (int dx = 0; dx < 3; dx++) {
            int px = x - dx;
            if (px >= 0 && px < 64) hB[px * 296 + kb + dx] = hv;
        }
    }
    __syncthreads();

    const int arow = w * 16 + (lane & 15);
    const int acolb = (lane >> 4) * 8;
    const uint4* gw[2];
    gw[0] = (const uint4*)g_wk2;
    gw[1] = (const uint4*)g_wv2;

#pragma unroll
    for (int mat = 0; mat < 2; mat++) {
        // stage folded weights (uint4 copies, 128x296 halves = 4736 uint4)
        uint4* ws = (uint4*)hW;
        for (int i = tid; i < 4736; i += 256) ws[i] = gw[mat][i];
        __syncthreads();

        float acc[2][4][4];
#pragma unroll
        for (int hf = 0; hf < 2; hf++)
#pragma unroll
            for (int nt = 0; nt < 4; nt++)
#pragma unroll
                for (int i = 0; i < 4; i++) acc[hf][nt][i] = 0.0f;
#pragma unroll 2
        for (int ks = 0; ks < 18; ks++) {
            uint32_t wa[4];
            ldsm4(wa, sb + W_OFF + (arow * 296 + ks * 16 + acolb) * 2);
#pragma unroll
            for (int hf = 0; hf < 2; hf++)
#pragma unroll
                for (int n0 = 0; n0 < 2; n0++) {
                    uint32_t bh[4];
                    ldsm4(bh, sb + B_OFF +
                          ((hf * 32 + n0 * 16 + brow) * 296 + ks * 16 + bcol8) * 2);
                    mma16816(acc[hf][n0 * 2], wa, bh);
                    mma16816(acc[hf][n0 * 2 + 1], wa, bh + 2);
                }
        }
        int coA = w * 16 + (lane >> 2);
        int coB = coA + 8;
        const float* be = mat ? g_bv2 : g_bk2;
        __half* H = mat ? g_vh : g_kh;
        float bA = be[coA], bB = be[coB];
#pragma unroll
        for (int hf = 0; hf < 2; hf++) {
            size_t baseA = ((size_t)b * CC + coA) * HW + y * 64 + hf * 32;
            size_t baseB = ((size_t)b * CC + coB) * HW + y * 64 + hf * 32;
#pragma unroll
            for (int nt = 0; nt < 4; nt++) {
                int px = nt * 8 + 2 * (lane & 3);
                *(uint32_t*)(H + baseA + px) =
                    cvt_f16x2(acc[hf][nt][1] + bA, acc[hf][nt][0] + bA);
                *(uint32_t*)(H + baseB + px) =
                    cvt_f16x2(acc[hf][nt][3] + bB, acc[hf][nt][2] + bB);
            }
        }
        if (mat == 0) __syncthreads();   // W reads done before re-stage
    }
}

// ================================================================
// flash attention (unchanged R16): fp16 QK/PV, lazy-max softmax,
// l via ones-column MMA, cross-tile pipeline, 4-stage cp.async ring.
// Epilogue writes fp16 pixel-major g_gdh.
// ================================================================
#define STAGE 17408
#define NSTAGE 4
#define SB_Q (NSTAGE * STAGE)
#define SBUF_BYTES (SB_Q + 8704)

__global__ void __launch_bounds__(256, 2) attn_mma() {
    extern __shared__ __align__(16) char sbuf[];
    const int tid = threadIdx.x;
    const int lane = tid & 31;
    const int w = tid >> 5;
    const int h = blockIdx.y, b = blockIdx.z;
    const int qb = blockIdx.x * 128;
    const size_t cbase = ((size_t)b * CC + h * 32) * HW;
    const __half* qgp = g_qh + cbase;
    const __half* kgp = g_kh + cbase;
    const __half* vgp = g_vh + cbase;
    const uint32_t sb = smem_u32(sbuf);

    const int cd = tid >> 3;
    const int cjh = (tid & 7) * 16;
    const uint32_t offK = (uint32_t)(cd * 136 + cjh) * 2;
    const uint32_t offV = 8704u + offK;
    const __half* gQ = qgp + (size_t)cd * HW + qb + cjh;
    const __half* gK = kgp + (size_t)cd * HW + cjh;
    const __half* gV = vgp + (size_t)cd * HW + cjh;
    cp16(sb + SB_Q + offK, gQ); cp16(sb + SB_Q + offK + 16, gQ + 8);
    CP_COMMIT();
    cp16(sb + offK, gK);       cp16(sb + offK + 16, gK + 8);
    cp16(sb + offV, gV);       cp16(sb + offV + 16, gV + 8);
    CP_COMMIT();
    cp16(sb + STAGE + offK, gK + 128); cp16(sb + STAGE + offK + 16, gK + 136);
    cp16(sb + STAGE + offV, gV + 128); cp16(sb + STAGE + offV + 16, gV + 136);
    CP_COMMIT();

    const int brow = (lane & 7) + ((lane & 16) >> 1);
    const int bcol8 = (lane & 8) ? 8 : 0;

    CP_WAIT2();
    __syncthreads();
    uint32_t qa[2][4];
#pragma unroll
    for (int ks = 0; ks < 2; ks++)
        ldsm4t(qa[ks], sb + SB_Q + ((ks * 16 + brow) * 136 + w * 16 + bcol8) * 2);

    const uint32_t b2c[2] = { (lane < 4) ? 0x3C003C00u : 0u,
                              (lane < 4) ? 0x3C003C00u : 0u };

    float mrow0 = 0.0f, mrow1 = 0.0f;
    float o[4][4], ol[4];
#pragma unroll
    for (int nt = 0; nt < 4; nt++)
#pragma unroll
        for (int i = 0; i < 4; i++) o[nt][i] = 0.0f;
#pragma unroll
    for (int i = 0; i < 4; i++) ol[i] = 0.0f;

    float s[8][4];
    uint32_t pu[8][2];

    auto s_init = [&]() {
        float ns0 = -mrow0, ns1 = -mrow1;
#pragma unroll
        for (int nt = 0; nt < 8; nt++) {
            s[nt][0] = ns0; s[nt][1] = ns0;
            s[nt][2] = ns1; s[nt][3] = ns1;
        }
    };
    auto qk_piece = [&](uint32_t base, int idx, int joff) {
        int ks = idx >> 2, n0 = idx & 3;
        uint32_t bh[4];
        ldsm4t(bh, base + ((ks * 16 + (lane & 15)) * 136 +
                           joff + n0 * 16 + (lane >> 4) * 8) * 2);
        mma16816(s[n0 * 2], qa[ks], bh);
        mma16816(s[n0 * 2 + 1], qa[ks], bh + 2);
    };
    auto pv_piece = [&](uint32_t base, int ks, int joff) {
        uint32_t ah[4] = { pu[2 * ks][0], pu[2 * ks][1],
                           pu[2 * ks + 1][0], pu[2 * ks + 1][1] };
#pragma unroll
        for (int n0 = 0; n0 < 2; n0++) {
            uint32_t vh[4];
            ldsm4(vh, base + 8704 + ((n0 * 16 + brow) * 136 +
                                     joff + ks * 16 + bcol8) * 2);
            mma16816(o[n0 * 2], ah, vh);
            mma16816(o[n0 * 2 + 1], ah, vh + 2);
        }
        mma16816(ol, ah, b2c);
    };
    auto softmax = [&]() {
        float mt0 = s[0][0], mt1 = s[0][2];
#pragma unroll
        for (int nt = 0; nt < 8; nt++) {
            mt0 = fmaxf(mt0, fmaxf(s[nt][0], s[nt][1]));
            mt1 = fmaxf(mt1, fmaxf(s[nt][2], s[nt][3]));
        }
        if (__any_sync(0xffffffffu, fmaxf(mt0, mt1) > 8.0f)) {
            mt0 = fmaxf(mt0, __shfl_xor_sync(0xffffffffu, mt0, 1));
            mt0 = fmaxf(mt0, __shfl_xor_sync(0xffffffffu, mt0, 2));
            mt1 = fmaxf(mt1, __shfl_xor_sync(0xffffffffu, mt1, 1));
            mt1 = fmaxf(mt1, __shfl_xor_sync(0xffffffffu, mt1, 2));
            float d0 = fmaxf(mt0, 0.0f), d1 = fmaxf(mt1, 0.0f);
            float c0 = ex2f(-d0), c1 = ex2f(-d1);
            mrow0 += d0; mrow1 += d1;
#pragma unroll
            for (int nt = 0; nt < 4; nt++) {
                o[nt][0] *= c0; o[nt][1] *= c0;
                o[nt][2] *= c1; o[nt][3] *= c1;
            }
            ol[0] *= c0; ol[1] *= c0; ol[2] *= c1; ol[3] *= c1;
#pragma unroll
            for (int nt = 0; nt < 8; nt++) {
                s[nt][0] -= d0; s[nt][1] -= d0;
                s[nt][2] -= d1; s[nt][3] -= d1;
            }
        }
#pragma unroll
        for (int nt = 0; nt < 8; nt++) {
            pu[nt][0] = ex2_h2(cvt_f16x2(s[nt][1], s[nt][0]));
            pu[nt][1] = ex2_h2(cvt_f16x2(s[nt][3], s[nt][2]));
        }
    };

    CP_WAIT1();
    __syncthreads();
    s_init();
#pragma unroll
    for (int i = 0; i < 8; i++) qk_piece(sb, i, 0);

#pragma unroll 4
    for (int t = 0; t < 32; t++) {
        const uint32_t bcur = sb + (uint32_t)(t & 3) * STAGE;
        const uint32_t bnxt = sb + (uint32_t)((t + 1) & 3) * STAGE;

        softmax();
        s_init();
#pragma unroll
        for (int ks = 0; ks < 4; ks++) {
            pv_piece(bcur, ks, 0);
            qk_piece(bcur, 2 * ks, 64);
            qk_piece(bcur, 2 * ks + 1, 64);
        }
        softmax();

        if (t + 2 < 32) {
            const uint32_t so = sb + (uint32_t)((t + 2) & 3) * STAGE;
            const int go = (t + 2) * 128;
            cp16(so + offK, gK + go);       cp16(so + offK + 16, gK + go + 8);
            cp16(so + offV, gV + go);       cp16(so + offV + 16, gV + go + 8);
        }
        CP_COMMIT();
        CP_WAIT1();
        __syncthreads();

        if (t < 31) {
            s_init();
#pragma unroll
            for (int ks = 0; ks < 4; ks++) {
                pv_piece(bcur, ks, 64);
                qk_piece(bnxt, 2 * ks, 0);
                qk_piece(bnxt, 2 * ks + 1, 0);
            }
        } else {
#pragma unroll
            for (int ks = 0; ks < 4; ks++) pv_piece(bcur, ks, 64);
        }
    }

    float l0 = __shfl_sync(0xffffffffu, ol[0], lane & 28);
    float l1 = __shfl_sync(0xffffffffu, ol[2], lane & 28);
    float i0 = 1.0f / l0, i1 = 1.0f / l1;
    int pix = qb + w * 16 + (lane >> 2);
    __half* og = g_gdh + ((size_t)b * HW + pix) * CC + h * 32;
#pragma unroll
    for (int nt = 0; nt < 4; nt++) {
        int d = nt * 8 + 2 * (lane & 3);
        *(uint32_t*)(og + d) = cvt_f16x2(o[nt][1] * i0, o[nt][0] * i0);
        *(uint32_t*)(og + 8 * CC + d) = cvt_f16x2(o[nt][3] * i1, o[nt][2] * i1);
    }
}

// ================================================================
// output conv: fp16 pixel-major X + residual (unchanged R16).
// ================================================================
__global__ __launch_bounds__(256) void conv_out(
    const __half* __restrict__ X,
    const float* __restrict__ W1, const float* __restrict__ b1,
    float* __restrict__ Y1, const float* __restrict__ resid) {
    __shared__ __align__(16) char sbufc[34816];
    const int tid = threadIdx.x;
    const int lane = tid & 31;
    const int w = tid >> 5;
    const int bb = blockIdx.y;
    const int p0 = blockIdx.x * 32;
    const uint32_t sb = smem_u32(sbufc);
    const int brow = (lane & 7) + ((lane & 16) >> 1);
    const int bcol8 = (lane & 8) ? 8 : 0;

    uint4 xreg[2];
#pragma unroll
    for (int i = 0; i < 2; i++) {
        int idx = i * 256 + tid;
        int px = idx >> 4, c16 = (idx & 15) * 8;
        xreg[i] = *(const uint4*)(X + ((size_t)bb * HW + p0 + px) * CC + c16);
    }

    uint32_t wa1[8][4];
    {
#pragma unroll
        for (int i = 0; i < 16; i++) {
            int idx = i * 256 + tid;
            int co = idx >> 5, ci = (idx & 31) * 4;
            float4 v = *(const float4*)(W1 + co * CC + ci);
            __half* d = (__half*)(sbufc) + co * 136 + ci;
            d[0] = __float2half(v.x); d[1] = __float2half(v.y);
            d[2] = __float2half(v.z); d[3] = __float2half(v.w);
        }
        __syncthreads();
        int row = w * 16 + (lane & 15);
        int colb = (lane >> 4) * 8;
#pragma unroll
        for (int ks = 0; ks < 8; ks++)
            ldsm4(wa1[ks], sb + (row * 136 + ks * 16 + colb) * 2);
        __syncthreads();
    }

#pragma unroll
    for (int i = 0; i < 2; i++) {
        int idx = i * 256 + tid;
        int px = idx >> 4, c16 = (idx & 15) * 8;
        *(uint4*)((__half*)(sbufc) + px * 136 + c16) = xreg[i];
    }
    __syncthreads();

    float acc1[4][4];
#pragma unroll
    for (int nt = 0; nt < 4; nt++)
#pragma unroll
        for (int i = 0; i < 4; i++) acc1[nt][i] = 0.0f;

#pragma unroll
    for (int ks = 0; ks < 8; ks++) {
#pragma unroll
        for (int n0 = 0; n0 < 2; n0++) {
            uint32_t bh[4];
            ldsm4(bh, sb + ((n0 * 16 + brow) * 136 + ks * 16 + bcol8) * 2);
            mma16816(acc1[n0 * 2], wa1[ks], bh);
            mma16816(acc1[n0 * 2 + 1], wa1[ks], bh + 2);
        }
    }

    int coA = w * 16 + (lane >> 2);
    int coB = coA + 8;
    float b1A = b1[coA], b1B = b1[coB];
    size_t baseA = ((size_t)bb * CC + coA) * HW + p0;
    size_t baseB = ((size_t)bb * CC + coB) * HW + p0;
#pragma unroll
    for (int nt = 0; nt < 4; nt++) {
        int px = nt * 8 + 2 * (lane & 3);
        float2 rA = *(const float2*)(resid + baseA + px);
        float2 rB = *(const float2*)(resid + baseB + px);
        *(float2*)(Y1 + baseA + px) =
            make_float2(acc1[nt][0] + b1A + rA.x, acc1[nt][1] + b1A + rA.y);
        *(float2*)(Y1 + baseB + px) =
            make_float2(acc1[nt][2] + b1B + rB.x, acc1[nt][3] + b1B + rB.y);
    }
}

// ---------------- launch ----------------
extern "C" void kernel_launch(void* const* d_in, const int* in_sizes, int n_in,
                              void* d_out, int out_size) {
    const float* sr  = (const float*)d_in[0];
    const float* seg = (const float*)d_in[1];
    const float* Wq  = (const float*)d_in[2];
    const float* bq  = (const float*)d_in[3];
    const float* Wm1 = (const float*)d_in[4];
    const float* bm1 = (const float*)d_in[5];
    const float* Wm2 = (const float*)d_in[6];
    const float* bm2 = (const float*)d_in[7];
    const float* Wk  = (const float*)d_in[8];
    const float* bk  = (const float*)d_in[9];
    const float* Wv  = (const float*)d_in[10];
    const float* bv  = (const float*)d_in[11];
    const float* Wo  = (const float*)d_in[12];
    const float* bo  = (const float*)d_in[13];
    float* out = (float*)d_out;

    __half* pgdh;
    cudaGetSymbolAddress((void**)&pgdh, g_gdh);

    cudaFuncSetAttribute(attn_mma, cudaFuncAttributeMaxDynamicSharedMemorySize,
                         SBUF_BYTES);
    cudaFuncSetAttribute(qkv_fused, cudaFuncAttributeMaxDynamicSharedMemorySize,
                         QKV_SMEM);

    precompute_w<<<dim3(288, 2), 128>>>(Wk, bk, Wv, bv, Wm2, bm2);
    qkv_fused<<<dim3(64, BATCH, 2), 256, QKV_SMEM>>>(sr, seg, Wm1, bm1, Wq, bq);
    attn_mma<<<dim3(32, HEADS, BATCH), 256, SBUF_BYTES>>>();
    conv_out<<<dim3(HW / 32, BATCH), 256>>>(pgdh, Wo, bo, out, sr);
}